// round 2
// baseline (speedup 1.0000x reference)
#include <cuda_runtime.h>
#include <math.h>

#define NB 64      // batch
#define NT 1024    // seq len
#define ND 256     // input dim
#define NH 1024    // hidden
#define NC 1000    // classes
#define RCTAS 128  // persistent recurrence CTAs

typedef unsigned long long u64;

// ---------------- scratch (device globals) ----------------
__device__ float g_xprojT[NT * NH * NB];     // [t][n][b]   256 MB
__device__ float g_hT[2 * NH * NB];          // [slot][n][b]
__device__ float g_zT[2 * 8 * NH * NB];      // [slot][kc][n][b]  4 MB
__device__ unsigned g_arr[8];                // producer arrivals per chunk (monotonic)
__device__ unsigned g_rcnt[8];               // reducer completions per chunk (monotonic)
__device__ unsigned g_hflag[8];              // steps completed per chunk (monotonic)

// ---------------- sync primitives ----------------
__device__ __forceinline__ unsigned ld_acq(const unsigned* p) {
    unsigned v;
    asm volatile("ld.global.acquire.gpu.u32 %0, [%1];" : "=r"(v) : "l"(p));
    return v;
}
__device__ __forceinline__ void st_rel(unsigned* p, unsigned v) {
    asm volatile("st.global.release.gpu.u32 [%0], %1;" :: "l"(p), "r"(v) : "memory");
}

// packed f32x2 FMA: d = a*b + d (elementwise on 2 packed fp32)
#define FMA2(d, a, b) asm("fma.rn.f32x2 %0, %1, %2, %0;" : "+l"(d) : "l"(a), "l"(b))

__device__ __forceinline__ float lo32(u64 v) { return __uint_as_float((unsigned)v); }
__device__ __forceinline__ float hi32(u64 v) { return __uint_as_float((unsigned)(v >> 32)); }

// ---------------- init: reset flags, zero h ----------------
__global__ void init_kernel() {
    int idx = blockIdx.x * 256 + threadIdx.x;
    for (int i = idx; i < 2 * NH * NB; i += 128 * 256) g_hT[i] = 0.0f;
    if (blockIdx.x == 0 && threadIdx.x < 8) {
        g_arr[threadIdx.x] = 0u;
        g_rcnt[threadIdx.x] = 0u;
        g_hflag[threadIdx.x] = 0u;
    }
}

// ---------------- classic fp32 tile core (used by xproj) ----------------
__device__ __forceinline__ void mm_tile(
    const float* A, int lda,
    const float* B, int ldb, int brows,
    int K, float acc[4][4],
    float (*As)[64], float (*Bs)[64])
{
    const int tid = threadIdx.x;
    const int tx = tid & 15, ty = tid >> 4;
    const int lr = tid >> 2, lc = tid & 3;
    const int br = (lr < brows) ? lr : (brows - 1);
    const float* Arow = A + (long)lr * lda;
    const float* Brow = B + (long)br * ldb;

    for (int k0 = 0; k0 < K; k0 += 32) {
        float4 a0 = __ldcg((const float4*)(Arow + k0 + lc * 4));
        float4 a1 = __ldcg((const float4*)(Arow + k0 + 16 + lc * 4));
        float4 b0 = __ldcg((const float4*)(Brow + k0 + lc * 4));
        float4 b1 = __ldcg((const float4*)(Brow + k0 + 16 + lc * 4));
        __syncthreads();
        As[lc * 4 + 0][lr] = a0.x;  As[lc * 4 + 1][lr] = a0.y;
        As[lc * 4 + 2][lr] = a0.z;  As[lc * 4 + 3][lr] = a0.w;
        As[lc * 4 + 16][lr] = a1.x; As[lc * 4 + 17][lr] = a1.y;
        As[lc * 4 + 18][lr] = a1.z; As[lc * 4 + 19][lr] = a1.w;
        Bs[lc * 4 + 0][lr] = b0.x;  Bs[lc * 4 + 1][lr] = b0.y;
        Bs[lc * 4 + 2][lr] = b0.z;  Bs[lc * 4 + 3][lr] = b0.w;
        Bs[lc * 4 + 16][lr] = b1.x; Bs[lc * 4 + 17][lr] = b1.y;
        Bs[lc * 4 + 18][lr] = b1.z; Bs[lc * 4 + 19][lr] = b1.w;
        __syncthreads();
        #pragma unroll
        for (int kk = 0; kk < 32; kk++) {
            float4 av = *(const float4*)(&As[kk][ty * 4]);
            float4 bv = *(const float4*)(&Bs[kk][tx * 4]);
            float a[4] = {av.x, av.y, av.z, av.w};
            float b[4] = {bv.x, bv.y, bv.z, bv.w};
            #pragma unroll
            for (int i = 0; i < 4; i++)
                #pragma unroll
                for (int j = 0; j < 4; j++)
                    acc[i][j] += a[i] * b[j];
        }
    }
}

// ---------------- kernel 1: xprojT[t][n][b] = x[b][t][:] . w_ih[n][:] ----------------
// blockIdx.x = t0 (one 64-batch slab per t), blockIdx.y = n tile.
__global__ __launch_bounds__(256) void xproj_kernel(
    const float* __restrict__ x, const float* __restrict__ w_ih)
{
    __shared__ float As[32][64];
    __shared__ float Bs[32][64];
    const int t0 = blockIdx.x;
    const int n0 = blockIdx.y * 64;
    float acc[4][4] = {};
    // A rows = batch b (stride NT*ND), fixed t0. acc[i][j] = z[b=ty*4+i][n=n0+tx*4+j]
    mm_tile(x + (long)t0 * ND, NT * ND, w_ih + (long)n0 * ND, ND, 64, ND, acc, As, Bs);

    const int tid = threadIdx.x;
    const int tx = tid & 15, ty = tid >> 4;
    #pragma unroll
    for (int j = 0; j < 4; j++) {
        float4 v = make_float4(acc[0][j], acc[1][j], acc[2][j], acc[3][j]);
        *(float4*)(g_xprojT + ((long)t0 * NH + n0 + tx * 4 + j) * NB + ty * 4) = v;
    }
}

// ---------------- kernel 2: persistent recurrence (f32x2, dataflow sync) ----------------
// CTA (nc = cta&15, kc = cta>>4). Persistent Bs = W_hh[nc*64..+64][kc*128..+128] in smem.
// Per step: wait hflag[kc] -> stage h chunk (duplicated) -> FFMA2 GEMM -> zT -> arrive
// -> wait arr[kc] -> reduce share of chunk kc -> hflag.
__global__ __launch_bounds__(256) void recur_kernel(
    const float* __restrict__ w_hh, const float* __restrict__ b_mod)
{
    extern __shared__ float sm[];
    float* As_dup = sm;                 // [128][128] floats, (h,h) duplicated pairs, 64 KB
    float* Bs = sm + 128 * 128;         // [128][64] floats (k-major), 32 KB

    const int tid = threadIdx.x;
    const int cta = blockIdx.x;
    const int nc = cta & 15;
    const int kc = cta >> 4;
    const int tx = tid & 15, ty = tid >> 4;
    const int myred = nc >> 1;          // chunk my zpart feeds

    // ---- one-time: load W_hh slice transposed into persistent smem ----
    #pragma unroll
    for (int it = 0; it < 8; it++) {
        int f4 = it * 256 + tid;                 // 2048 float4 = 8192 floats
        int np = f4 >> 5, k0 = (f4 & 31) * 4;
        float4 w = __ldg((const float4*)(w_hh + (long)(nc * 64 + np) * NH + kc * 128 + k0));
        Bs[(k0 + 0) * 64 + np] = w.x;
        Bs[(k0 + 1) * 64 + np] = w.y;
        Bs[(k0 + 2) * 64 + np] = w.z;
        Bs[(k0 + 3) * 64 + np] = w.w;
    }
    __syncthreads();

    for (int t = 0; t < NT; t++) {
        const int slot = t & 1, pslot = slot ^ 1;

        // ---- wait: h_{t-1} chunk kc ready; zpart slot consumed (WAR) ----
        if (tid == 0) {
            if (t > 0) while ((int)ld_acq(&g_hflag[kc]) < t) {}
            if (t > 1) while ((int)ld_acq(&g_hflag[myred]) < t - 1) {}
        }
        __syncthreads();

        // ---- stage h chunk, duplicated: As_dup[k][2b..2b+1] = h[b][kc*128+k] ----
        {
            const float2* hsrc = (const float2*)(g_hT + pslot * (NH * NB) + kc * 128 * NB);
            float4* Ad4 = (float4*)As_dup;
            #pragma unroll
            for (int it = 0; it < 16; it++) {
                int f2 = it * 256 + tid;
                float2 v = __ldcg(&hsrc[f2]);
                Ad4[f2] = make_float4(v.x, v.x, v.y, v.y);
            }
        }
        __syncthreads();

        // ---- GEMM: acc2[i][jp] pairs along n; 8 FFMA2 + 3 LDS.128 per kk ----
        u64 acc[4][2];
        #pragma unroll
        for (int i = 0; i < 4; i++) { acc[i][0] = 0ull; acc[i][1] = 0ull; }

        #pragma unroll 8
        for (int kk = 0; kk < 128; kk++) {
            const ulonglong2 bp  = *(const ulonglong2*)(Bs + kk * 64 + tx * 4);
            const ulonglong2 a01 = *(const ulonglong2*)(As_dup + kk * 128 + ty * 8);
            const ulonglong2 a23 = *(const ulonglong2*)(As_dup + kk * 128 + ty * 8 + 4);
            FMA2(acc[0][0], a01.x, bp.x); FMA2(acc[0][1], a01.x, bp.y);
            FMA2(acc[1][0], a01.y, bp.x); FMA2(acc[1][1], a01.y, bp.y);
            FMA2(acc[2][0], a23.x, bp.x); FMA2(acc[2][1], a23.x, bp.y);
            FMA2(acc[3][0], a23.y, bp.x); FMA2(acc[3][1], a23.y, bp.y);
        }

        // ---- store zT[slot][kc][n][b] : float4 along b for each j ----
        {
            float* zb = g_zT + (long)(slot * 8 + kc) * (NH * NB);
            #pragma unroll
            for (int j = 0; j < 4; j++) {
                int jp = j >> 1;
                float4 v;
                if (j & 1) v = make_float4(hi32(acc[0][jp]), hi32(acc[1][jp]),
                                           hi32(acc[2][jp]), hi32(acc[3][jp]));
                else       v = make_float4(lo32(acc[0][jp]), lo32(acc[1][jp]),
                                           lo32(acc[2][jp]), lo32(acc[3][jp]));
                __stcg((float4*)(zb + (long)(nc * 64 + tx * 4 + j) * NB + ty * 4), v);
            }
        }
        __threadfence();
        __syncthreads();
        if (tid == 0) atomicAdd(&g_arr[myred], 1u);

        // ---- reduce duty: wait all 16 producers of chunk kc ----
        if (tid == 0) while ((int)ld_acq(&g_arr[kc]) < 16 * (t + 1)) {}
        __syncthreads();
        {
            int f2 = nc * 256 + tid;                  // this CTA's 256 float2 of chunk kc
            int n = kc * 128 + (f2 >> 5);
            int g2 = n * 32 + (f2 & 31);              // float2 index in [n][b]
            const float2* xp2 = (const float2*)(g_xprojT + (long)t * (NH * NB));
            float2 z = __ldcg(&xp2[g2]);
            #pragma unroll
            for (int s = 0; s < 8; s++) {
                float2 p = __ldcg((const float2*)(g_zT + (long)(slot * 8 + s) * (NH * NB)) + g2);
                z.x += p.x; z.y += p.y;
            }
            float bm = __ldg(&b_mod[n]);
            float ax = fabsf(z.x) + bm;
            float ay = fabsf(z.y) + bm;
            float2 h;
            h.x = (ax > 0.0f) ? copysignf(ax, z.x) : 0.0f;
            h.y = (ay > 0.0f) ? copysignf(ay, z.y) : 0.0f;
            __stcg((float2*)(g_hT + slot * (NH * NB)) + g2, h);
        }
        __threadfence();
        __syncthreads();
        if (tid == 0) {
            unsigned prev = atomicAdd(&g_rcnt[kc], 1u);
            if (prev == (unsigned)(16 * (t + 1) - 1)) st_rel(&g_hflag[kc], (unsigned)(t + 1));
        }
    }
}

// ---------------- kernel 3: fc head out[b][c] = h_last[b][:] . w_fc[c][:] + b_fc[c] ----
__global__ __launch_bounds__(256) void fc_kernel(
    const float* __restrict__ w_fc, const float* __restrict__ b_fc,
    float* __restrict__ out)
{
    __shared__ float As[64][64];   // [k][b] slab of h_T
    __shared__ float Bs[64][64];   // [k][c']
    const int n0 = blockIdx.x * 64;
    const int tid = threadIdx.x;
    const int tx = tid & 15, ty = tid >> 4;
    const float* hT = g_hT + ((NT - 1) & 1) * (NH * NB);   // h after last step
    float acc[4][4] = {};

    for (int s = 0; s < 16; s++) {
        __syncthreads();
        #pragma unroll
        for (int it = 0; it < 4; it++) {
            int f4 = it * 256 + tid;     // 1024 float4 = 4096 floats
            ((float4*)As)[f4] = *((const float4*)(hT + s * 64 * NB) + f4);
        }
        #pragma unroll
        for (int it = 0; it < 4; it++) {
            int f4 = it * 256 + tid;
            int np = f4 >> 4, k0 = (f4 & 15) * 4;
            int row = n0 + np; if (row >= NC) row = NC - 1;
            float4 w = *(const float4*)(w_fc + (long)row * NH + s * 64 + k0);
            Bs[k0 + 0][np] = w.x; Bs[k0 + 1][np] = w.y;
            Bs[k0 + 2][np] = w.z; Bs[k0 + 3][np] = w.w;
        }
        __syncthreads();
        #pragma unroll 8
        for (int kk = 0; kk < 64; kk++) {
            float4 av = *(const float4*)(&As[kk][ty * 4]);
            float4 bv = *(const float4*)(&Bs[kk][tx * 4]);
            float a[4] = {av.x, av.y, av.z, av.w};
            float b[4] = {bv.x, bv.y, bv.z, bv.w};
            #pragma unroll
            for (int i = 0; i < 4; i++)
                #pragma unroll
                for (int j = 0; j < 4; j++)
                    acc[i][j] += a[i] * b[j];
        }
    }
    #pragma unroll
    for (int i = 0; i < 4; i++) {
        #pragma unroll
        for (int j = 0; j < 4; j++) {
            int c = n0 + tx * 4 + j;
            if (c < NC) out[(long)(ty * 4 + i) * NC + c] = acc[i][j] + __ldg(&b_fc[c]);
        }
    }
}

// ---------------- launch ----------------
extern "C" void kernel_launch(void* const* d_in, const int* in_sizes, int n_in,
                              void* d_out, int out_size)
{
    const float* x     = (const float*)d_in[0];  // [64,1024,256]
    const float* w_ih  = (const float*)d_in[1];  // [1024,256]
    const float* w_hh  = (const float*)d_in[2];  // [1024,1024]
    const float* b_mod = (const float*)d_in[3];  // [1024]
    const float* w_fc  = (const float*)d_in[4];  // [1000,1024]
    const float* b_fc  = (const float*)d_in[5];  // [1000]
    float* out = (float*)d_out;                  // [64,1000]

    cudaFuncSetAttribute(recur_kernel, cudaFuncAttributeMaxDynamicSharedMemorySize, 98304);

    init_kernel<<<128, 256>>>();
    dim3 gx(NT, NH / 64);
    xproj_kernel<<<gx, 256>>>(x, w_ih);
    recur_kernel<<<RCTAS, 256, 98304>>>(w_hh, b_mod);
    fc_kernel<<<(NC + 63) / 64, 256>>>(w_fc, b_fc, out);
}

// round 3
// speedup vs baseline: 1.2626x; 1.2626x over previous
#include <cuda_runtime.h>
#include <math.h>

#define NB 64      // batch
#define NT 1024    // seq len
#define ND 256     // input dim
#define NH 1024    // hidden
#define NC 1000    // classes
#define RCTAS 128  // persistent recurrence CTAs (1 CTA/SM guaranteed resident)

typedef unsigned long long u64;

// ---------------- scratch (device globals) ----------------
__device__ float g_xprojT[NT * NH * NB];   // [t][n][b]  256 MB
__device__ float g_hT[NH * NB];            // [n][b]
__device__ float g_zT[8 * NH * NB];        // [kc][n][b] split-K partials, 2 MB
__device__ unsigned g_bar_count;
__device__ unsigned g_bar_gen;

// ---------------- software grid barrier (R1-proven) ----------------
__device__ __forceinline__ void gsync(unsigned nb) {
    __syncthreads();
    if (threadIdx.x == 0) {
        __threadfence();
        unsigned g = atomicOr(&g_bar_gen, 0u);
        if (atomicAdd(&g_bar_count, 1u) == nb - 1u) {
            atomicExch(&g_bar_count, 0u);
            __threadfence();
            atomicExch(&g_bar_gen, g + 1u);
        } else {
            while (atomicOr(&g_bar_gen, 0u) == g) { __nanosleep(64); }
        }
        __threadfence();
    }
    __syncthreads();
}

// packed f32x2 FMA: d = a*b + d
#define FMA2(d, a, b) asm("fma.rn.f32x2 %0, %1, %2, %0;" : "+l"(d) : "l"(a), "l"(b))
__device__ __forceinline__ float lo32(u64 v) { return __uint_as_float((unsigned)v); }
__device__ __forceinline__ float hi32(u64 v) { return __uint_as_float((unsigned)(v >> 32)); }

// ---------------- classic fp32 tile core (xproj only) ----------------
__device__ __forceinline__ void mm_tile(
    const float* A, int lda,
    const float* B, int ldb, int brows,
    int K, float acc[4][4],
    float (*As)[64], float (*Bs)[64])
{
    const int tid = threadIdx.x;
    const int tx = tid & 15, ty = tid >> 4;
    const int lr = tid >> 2, lc = tid & 3;
    const int br = (lr < brows) ? lr : (brows - 1);
    const float* Arow = A + (long)lr * lda;
    const float* Brow = B + (long)br * ldb;

    for (int k0 = 0; k0 < K; k0 += 32) {
        float4 a0 = __ldcg((const float4*)(Arow + k0 + lc * 4));
        float4 a1 = __ldcg((const float4*)(Arow + k0 + 16 + lc * 4));
        float4 b0 = __ldcg((const float4*)(Brow + k0 + lc * 4));
        float4 b1 = __ldcg((const float4*)(Brow + k0 + 16 + lc * 4));
        __syncthreads();
        As[lc * 4 + 0][lr] = a0.x;  As[lc * 4 + 1][lr] = a0.y;
        As[lc * 4 + 2][lr] = a0.z;  As[lc * 4 + 3][lr] = a0.w;
        As[lc * 4 + 16][lr] = a1.x; As[lc * 4 + 17][lr] = a1.y;
        As[lc * 4 + 18][lr] = a1.z; As[lc * 4 + 19][lr] = a1.w;
        Bs[lc * 4 + 0][lr] = b0.x;  Bs[lc * 4 + 1][lr] = b0.y;
        Bs[lc * 4 + 2][lr] = b0.z;  Bs[lc * 4 + 3][lr] = b0.w;
        Bs[lc * 4 + 16][lr] = b1.x; Bs[lc * 4 + 17][lr] = b1.y;
        Bs[lc * 4 + 18][lr] = b1.z; Bs[lc * 4 + 19][lr] = b1.w;
        __syncthreads();
        #pragma unroll
        for (int kk = 0; kk < 32; kk++) {
            float4 av = *(const float4*)(&As[kk][ty * 4]);
            float4 bv = *(const float4*)(&Bs[kk][tx * 4]);
            float a[4] = {av.x, av.y, av.z, av.w};
            float b[4] = {bv.x, bv.y, bv.z, bv.w};
            #pragma unroll
            for (int i = 0; i < 4; i++)
                #pragma unroll
                for (int j = 0; j < 4; j++)
                    acc[i][j] += a[i] * b[j];
        }
    }
}

// ---------------- kernel 1: xprojT[t][n][b] = x[b][t][:] . w_ih[n][:] ----------------
__global__ __launch_bounds__(256) void xproj_kernel(
    const float* __restrict__ x, const float* __restrict__ w_ih)
{
    __shared__ float As[32][64];
    __shared__ float Bs[32][64];
    const int t0 = blockIdx.x;
    const int n0 = blockIdx.y * 64;
    float acc[4][4] = {};
    mm_tile(x + (long)t0 * ND, NT * ND, w_ih + (long)n0 * ND, ND, 64, ND, acc, As, Bs);

    const int tid = threadIdx.x;
    const int tx = tid & 15, ty = tid >> 4;
    #pragma unroll
    for (int j = 0; j < 4; j++) {
        float4 v = make_float4(acc[0][j], acc[1][j], acc[2][j], acc[3][j]);
        *(float4*)(g_xprojT + ((long)t0 * NH + n0 + tx * 4 + j) * NB + ty * 4) = v;
    }
}

// ---------------- kernel 2: persistent recurrence ----------------
// CTA (nc = cta&15, kc = cta>>4). Persistent Bs = W_hh[nc*64..+64][kc*128..+128] in smem.
// Per step: stage h chunk (dup) -> FFMA2 GEMM -> zT -> barrier -> reduce+modReLU -> barrier.
__global__ __launch_bounds__(256) void recur_kernel(
    const float* __restrict__ w_hh, const float* __restrict__ b_mod)
{
    extern __shared__ float sm[];
    float* As_dup = sm;                 // [128][128] floats, (h,h) duplicated pairs, 64 KB
    float* Bs = sm + 128 * 128;         // [128][64] floats (k-major), 32 KB

    const int tid = threadIdx.x;
    const int cta = blockIdx.x;
    const int nc = cta & 15;
    const int kc = cta >> 4;
    const int tx = tid & 15, ty = tid >> 4;

    // ---- one-time: W_hh slice transposed into persistent smem ----
    #pragma unroll
    for (int it = 0; it < 8; it++) {
        int f4 = it * 256 + tid;                 // 2048 float4 = 8192 floats
        int np = f4 >> 5, k0 = (f4 & 31) * 4;
        float4 w = __ldg((const float4*)(w_hh + (long)(nc * 64 + np) * NH + kc * 128 + k0));
        Bs[(k0 + 0) * 64 + np] = w.x;
        Bs[(k0 + 1) * 64 + np] = w.y;
        Bs[(k0 + 2) * 64 + np] = w.z;
        Bs[(k0 + 3) * 64 + np] = w.w;
    }

    // ---- h = 0 ----
    for (int i = cta * 256 + tid; i < NH * NB; i += RCTAS * 256) g_hT[i] = 0.0f;
    gsync(RCTAS);

    float* zbase = g_zT + (long)kc * (NH * NB) + (long)(nc * 64) * NB;

    for (int t = 0; t < NT; t++) {
        // ---- stage h chunk kc, duplicated: As_dup[k][2b,2b+1] = h[kc*128+k][b] ----
        {
            const float2* hsrc = (const float2*)(g_hT + kc * 128 * NB);
            float4* Ad4 = (float4*)As_dup;
            #pragma unroll
            for (int it = 0; it < 16; it++) {
                int f2 = it * 256 + tid;
                float2 v = __ldcg(&hsrc[f2]);
                Ad4[f2] = make_float4(v.x, v.x, v.y, v.y);
            }
        }
        __syncthreads();

        // ---- GEMM: 128 kk x (3 LDS.128 + 8 FFMA2) ----
        u64 acc[4][2];
        #pragma unroll
        for (int i = 0; i < 4; i++) { acc[i][0] = 0ull; acc[i][1] = 0ull; }

        #pragma unroll 8
        for (int kk = 0; kk < 128; kk++) {
            const ulonglong2 bp  = *(const ulonglong2*)(Bs + kk * 64 + tx * 4);
            const ulonglong2 a01 = *(const ulonglong2*)(As_dup + kk * 128 + ty * 8);
            const ulonglong2 a23 = *(const ulonglong2*)(As_dup + kk * 128 + ty * 8 + 4);
            FMA2(acc[0][0], a01.x, bp.x); FMA2(acc[0][1], a01.x, bp.y);
            FMA2(acc[1][0], a01.y, bp.x); FMA2(acc[1][1], a01.y, bp.y);
            FMA2(acc[2][0], a23.x, bp.x); FMA2(acc[2][1], a23.x, bp.y);
            FMA2(acc[3][0], a23.y, bp.x); FMA2(acc[3][1], a23.y, bp.y);
        }

        // ---- store partials zT[kc][n][b] ----
        #pragma unroll
        for (int j = 0; j < 4; j++) {
            int jp = j >> 1;
            float4 v;
            if (j & 1) v = make_float4(hi32(acc[0][jp]), hi32(acc[1][jp]),
                                       hi32(acc[2][jp]), hi32(acc[3][jp]));
            else       v = make_float4(lo32(acc[0][jp]), lo32(acc[1][jp]),
                                       lo32(acc[2][jp]), lo32(acc[3][jp]));
            __stcg((float4*)(zbase + (long)(tx * 4 + j) * NB + ty * 4), v);
        }
        gsync(RCTAS);   // all partials visible

        // ---- reduce + modReLU: 128 float4 per CTA over the whole h ----
        if (tid < 128) {
            int g4 = cta * 128 + tid;            // float4 index in [n][b] space
            int n = g4 >> 4;
            const float4* xp4 = (const float4*)(g_xprojT + (long)t * (NH * NB));
            float4 z = __ldcg(&xp4[g4]);
            #pragma unroll
            for (int s = 0; s < 8; s++) {
                float4 p = __ldcg((const float4*)(g_zT + (long)s * (NH * NB)) + g4);
                z.x += p.x; z.y += p.y; z.z += p.z; z.w += p.w;
            }
            float bm = __ldg(&b_mod[n]);
            float4 h;
            float a;
            a = fabsf(z.x) + bm; h.x = (a > 0.0f) ? copysignf(a, z.x) : 0.0f;
            a = fabsf(z.y) + bm; h.y = (a > 0.0f) ? copysignf(a, z.y) : 0.0f;
            a = fabsf(z.z) + bm; h.z = (a > 0.0f) ? copysignf(a, z.z) : 0.0f;
            a = fabsf(z.w) + bm; h.w = (a > 0.0f) ? copysignf(a, z.w) : 0.0f;
            __stcg((float4*)g_hT + g4, h);
        }
        gsync(RCTAS);   // h_t visible everywhere
    }
}

// ---------------- kernel 3: fc head out[b][c] = h_last[b][:] . w_fc[c][:] + b_fc[c] ----
__global__ __launch_bounds__(256) void fc_kernel(
    const float* __restrict__ w_fc, const float* __restrict__ b_fc,
    float* __restrict__ out)
{
    __shared__ float As[64][64];   // [k][b]
    __shared__ float Bs[64][64];   // [k][c']
    const int n0 = blockIdx.x * 64;
    const int tid = threadIdx.x;
    const int tx = tid & 15, ty = tid >> 4;
    float acc[4][4] = {};

    for (int s = 0; s < 16; s++) {
        __syncthreads();
        #pragma unroll
        for (int it = 0; it < 4; it++) {
            int f4 = it * 256 + tid;
            ((float4*)As)[f4] = __ldcg((const float4*)(g_hT + s * 64 * NB) + f4);
        }
        #pragma unroll
        for (int it = 0; it < 4; it++) {
            int f4 = it * 256 + tid;
            int np = f4 >> 4, k0 = (f4 & 15) * 4;
            int row = n0 + np; if (row >= NC) row = NC - 1;
            float4 w = *(const float4*)(w_fc + (long)row * NH + s * 64 + k0);
            Bs[k0 + 0][np] = w.x; Bs[k0 + 1][np] = w.y;
            Bs[k0 + 2][np] = w.z; Bs[k0 + 3][np] = w.w;
        }
        __syncthreads();
        #pragma unroll 8
        for (int kk = 0; kk < 64; kk++) {
            float4 av = *(const float4*)(&As[kk][ty * 4]);
            float4 bv = *(const float4*)(&Bs[kk][tx * 4]);
            float a[4] = {av.x, av.y, av.z, av.w};
            float b[4] = {bv.x, bv.y, bv.z, bv.w};
            #pragma unroll
            for (int i = 0; i < 4; i++)
                #pragma unroll
                for (int j = 0; j < 4; j++)
                    acc[i][j] += a[i] * b[j];
        }
    }
    #pragma unroll
    for (int i = 0; i < 4; i++) {
        #pragma unroll
        for (int j = 0; j < 4; j++) {
            int c = n0 + tx * 4 + j;
            if (c < NC) out[(long)(ty * 4 + i) * NC + c] = acc[i][j] + __ldg(&b_fc[c]);
        }
    }
}

// ---------------- launch ----------------
extern "C" void kernel_launch(void* const* d_in, const int* in_sizes, int n_in,
                              void* d_out, int out_size)
{
    const float* x     = (const float*)d_in[0];  // [64,1024,256]
    const float* w_ih  = (const float*)d_in[1];  // [1024,256]
    const float* w_hh  = (const float*)d_in[2];  // [1024,1024]
    const float* b_mod = (const float*)d_in[3];  // [1024]
    const float* w_fc  = (const float*)d_in[4];  // [1000,1024]
    const float* b_fc  = (const float*)d_in[5];  // [1000]
    float* out = (float*)d_out;                  // [64,1000]

    cudaFuncSetAttribute(recur_kernel, cudaFuncAttributeMaxDynamicSharedMemorySize, 98304);

    dim3 gx(NT, NH / 64);
    xproj_kernel<<<gx, 256>>>(x, w_ih);
    recur_kernel<<<RCTAS, 256, 98304>>>(w_hh, b_mod);
    fc_kernel<<<(NC + 63) / 64, 256>>>(w_fc, b_fc, out);
}

// round 4
// speedup vs baseline: 1.5260x; 1.2086x over previous
#include <cuda_runtime.h>
#include <math.h>

#define NB 64      // batch
#define NT 1024    // seq len
#define ND 256     // input dim
#define NH 1024    // hidden
#define NC 1000    // classes
#define RCTAS 128  // persistent recurrence CTAs (1 CTA/SM resident)

typedef unsigned long long u64;

// ---------------- scratch (device globals) ----------------
// z buffers: initialized to xproj by xproj_kernel, then the recurrence
// red-accumulates W_hh*h_{t-1} into slice t. h_t = modrelu(z_t) is computed
// on the fly by readers (stage / fc).
__device__ float g_xprojT[NT * NH * NB];   // [t][n][b]  256 MB
__device__ unsigned g_arr[8];              // group arrival counters (monotonic per launch)
__device__ unsigned g_root;                // root counter
__device__ unsigned g_gen;                 // completed-step generation

// ---------------- sync primitives ----------------
__device__ __forceinline__ unsigned ld_acq(const unsigned* p) {
    unsigned v;
    asm volatile("ld.global.acquire.gpu.u32 %0, [%1];" : "=r"(v) : "l"(p));
    return v;
}
__device__ __forceinline__ void st_rel(unsigned* p, unsigned v) {
    asm volatile("st.global.release.gpu.u32 [%0], %1;" :: "l"(p), "r"(v) : "memory");
}

// packed f32x2 FMA: d = a*b + d
#define FMA2(d, a, b) asm("fma.rn.f32x2 %0, %1, %2, %0;" : "+l"(d) : "l"(a), "l"(b))
__device__ __forceinline__ float lo32(u64 v) { return __uint_as_float((unsigned)v); }
__device__ __forceinline__ float hi32(u64 v) { return __uint_as_float((unsigned)(v >> 32)); }

__device__ __forceinline__ float modrelu(float z, float bm) {
    float a = fabsf(z) + bm;
    return (a > 0.0f) ? copysignf(a, z) : 0.0f;
}

// ---------------- init: reset barrier counters each launch ----------------
__global__ void init_kernel() {
    if (threadIdx.x < 8) g_arr[threadIdx.x] = 0u;
    if (threadIdx.x == 8) g_root = 0u;
    if (threadIdx.x == 9) g_gen = 0u;
}

// ---------------- classic fp32 tile core (xproj only) ----------------
__device__ __forceinline__ void mm_tile(
    const float* A, int lda,
    const float* B, int ldb, int brows,
    int K, float acc[4][4],
    float (*As)[64], float (*Bs)[64])
{
    const int tid = threadIdx.x;
    const int tx = tid & 15, ty = tid >> 4;
    const int lr = tid >> 2, lc = tid & 3;
    const int br = (lr < brows) ? lr : (brows - 1);
    const float* Arow = A + (long)lr * lda;
    const float* Brow = B + (long)br * ldb;

    for (int k0 = 0; k0 < K; k0 += 32) {
        float4 a0 = __ldcg((const float4*)(Arow + k0 + lc * 4));
        float4 a1 = __ldcg((const float4*)(Arow + k0 + 16 + lc * 4));
        float4 b0 = __ldcg((const float4*)(Brow + k0 + lc * 4));
        float4 b1 = __ldcg((const float4*)(Brow + k0 + 16 + lc * 4));
        __syncthreads();
        As[lc * 4 + 0][lr] = a0.x;  As[lc * 4 + 1][lr] = a0.y;
        As[lc * 4 + 2][lr] = a0.z;  As[lc * 4 + 3][lr] = a0.w;
        As[lc * 4 + 16][lr] = a1.x; As[lc * 4 + 17][lr] = a1.y;
        As[lc * 4 + 18][lr] = a1.z; As[lc * 4 + 19][lr] = a1.w;
        Bs[lc * 4 + 0][lr] = b0.x;  Bs[lc * 4 + 1][lr] = b0.y;
        Bs[lc * 4 + 2][lr] = b0.z;  Bs[lc * 4 + 3][lr] = b0.w;
        Bs[lc * 4 + 16][lr] = b1.x; Bs[lc * 4 + 17][lr] = b1.y;
        Bs[lc * 4 + 18][lr] = b1.z; Bs[lc * 4 + 19][lr] = b1.w;
        __syncthreads();
        #pragma unroll
        for (int kk = 0; kk < 32; kk++) {
            float4 av = *(const float4*)(&As[kk][ty * 4]);
            float4 bv = *(const float4*)(&Bs[kk][tx * 4]);
            float a[4] = {av.x, av.y, av.z, av.w};
            float b[4] = {bv.x, bv.y, bv.z, bv.w};
            #pragma unroll
            for (int i = 0; i < 4; i++)
                #pragma unroll
                for (int j = 0; j < 4; j++)
                    acc[i][j] += a[i] * b[j];
        }
    }
}

// ---------------- kernel 1: xprojT[t][n][b] = x[b][t][:] . w_ih[n][:] ----------------
__global__ __launch_bounds__(256) void xproj_kernel(
    const float* __restrict__ x, const float* __restrict__ w_ih)
{
    __shared__ float As[32][64];
    __shared__ float Bs[32][64];
    const int t0 = blockIdx.x;
    const int n0 = blockIdx.y * 64;
    float acc[4][4] = {};
    mm_tile(x + (long)t0 * ND, NT * ND, w_ih + (long)n0 * ND, ND, 64, ND, acc, As, Bs);

    const int tid = threadIdx.x;
    const int tx = tid & 15, ty = tid >> 4;
    #pragma unroll
    for (int j = 0; j < 4; j++) {
        float4 v = make_float4(acc[0][j], acc[1][j], acc[2][j], acc[3][j]);
        *(float4*)(g_xprojT + ((long)t0 * NH + n0 + tx * 4 + j) * NB + ty * 4) = v;
    }
}

// ---------------- kernel 2: persistent recurrence (1 barrier/step) ----------------
// CTA (nc = cta&15, kc = cta>>4). Persistent Bs = W_hh[nc*64..+64][kc*128..+128].
// Step t (t=1..NT-1):
//   stage: h = modrelu(z_{t-1}) chunk kc, duplicated into smem
//   GEMM (FFMA2) -> partial z
//   red.add partials into g_xprojT[t]
//   two-level grid barrier (acquire-load spin)
__global__ __launch_bounds__(256) void recur_kernel(
    const float* __restrict__ w_hh, const float* __restrict__ b_mod)
{
    extern __shared__ float sm[];
    float* As_dup = sm;                 // [128][128] floats, (h,h) duplicated pairs, 64 KB
    float* Bs = sm + 128 * 128;         // [128][64] floats (k-major), 32 KB

    const int tid = threadIdx.x;
    const int cta = blockIdx.x;
    const int nc = cta & 15;
    const int kc = cta >> 4;
    const int tx = tid & 15, ty = tid >> 4;

    // ---- one-time: W_hh slice transposed into persistent smem ----
    #pragma unroll
    for (int it = 0; it < 8; it++) {
        int f4 = it * 256 + tid;                 // 2048 float4 = 8192 floats
        int np = f4 >> 5, k0 = (f4 & 31) * 4;
        float4 w = __ldg((const float4*)(w_hh + (long)(nc * 64 + np) * NH + kc * 128 + k0));
        Bs[(k0 + 0) * 64 + np] = w.x;
        Bs[(k0 + 1) * 64 + np] = w.y;
        Bs[(k0 + 2) * 64 + np] = w.z;
        Bs[(k0 + 3) * 64 + np] = w.w;
    }
    __syncthreads();

    for (int t = 1; t < NT; t++) {
        // ---- stage: h_{t-1} = modrelu(z_{t-1}) chunk kc, duplicated ----
        {
            const float2* zsrc = (const float2*)(g_xprojT +
                                 ((long)(t - 1) * NH + kc * 128) * NB);
            float4* Ad4 = (float4*)As_dup;
            #pragma unroll
            for (int it = 0; it < 16; it++) {
                int f2 = it * 256 + tid;
                int n = kc * 128 + (f2 >> 5);
                float2 z = __ldcg(&zsrc[f2]);
                float bm = __ldg(&b_mod[n]);
                float hx = modrelu(z.x, bm);
                float hy = modrelu(z.y, bm);
                Ad4[f2] = make_float4(hx, hx, hy, hy);
            }
        }
        __syncthreads();

        // ---- GEMM: 128 kk x (3 LDS.128 + 8 FFMA2) ----
        u64 acc[4][2];
        #pragma unroll
        for (int i = 0; i < 4; i++) { acc[i][0] = 0ull; acc[i][1] = 0ull; }

        #pragma unroll 8
        for (int kk = 0; kk < 128; kk++) {
            const ulonglong2 bp  = *(const ulonglong2*)(Bs + kk * 64 + tx * 4);
            const ulonglong2 a01 = *(const ulonglong2*)(As_dup + kk * 128 + ty * 8);
            const ulonglong2 a23 = *(const ulonglong2*)(As_dup + kk * 128 + ty * 8 + 4);
            FMA2(acc[0][0], a01.x, bp.x); FMA2(acc[0][1], a01.x, bp.y);
            FMA2(acc[1][0], a01.y, bp.x); FMA2(acc[1][1], a01.y, bp.y);
            FMA2(acc[2][0], a23.x, bp.x); FMA2(acc[2][1], a23.x, bp.y);
            FMA2(acc[3][0], a23.y, bp.x); FMA2(acc[3][1], a23.y, bp.y);
        }

        // ---- red-accumulate partials into z_t ----
        {
            float* zdst = g_xprojT + ((long)t * NH + nc * 64) * NB;
            #pragma unroll
            for (int j = 0; j < 4; j++) {
                int jp = j >> 1;
                float v0, v1, v2, v3;
                if (j & 1) { v0 = hi32(acc[0][jp]); v1 = hi32(acc[1][jp]);
                             v2 = hi32(acc[2][jp]); v3 = hi32(acc[3][jp]); }
                else       { v0 = lo32(acc[0][jp]); v1 = lo32(acc[1][jp]);
                             v2 = lo32(acc[2][jp]); v3 = lo32(acc[3][jp]); }
                float* p = zdst + (long)(tx * 4 + j) * NB + ty * 4;
                atomicAdd(p + 0, v0); atomicAdd(p + 1, v1);
                atomicAdd(p + 2, v2); atomicAdd(p + 3, v3);
            }
        }

        // ---- grid barrier for step t (two-level arrive, acquire-load spin) ----
        __syncthreads();
        if (tid == 0) {
            __threadfence();   // drain reds before arrival
            unsigned old = atomicAdd(&g_arr[cta & 7], 1u);
            if (old == (unsigned)(t * 16 - 1)) {
                if (atomicAdd(&g_root, 1u) == (unsigned)(t * 8 - 1))
                    st_rel(&g_gen, (unsigned)t);
            }
            while ((int)ld_acq(&g_gen) < t) { __nanosleep(32); }
        }
        __syncthreads();
    }
}

// ---------------- kernel 3: fc head out[b][c] = modrelu(z_last)[:,b] . w_fc[c][:] + b_fc[c]
__global__ __launch_bounds__(256) void fc_kernel(
    const float* __restrict__ w_fc, const float* __restrict__ b_fc,
    const float* __restrict__ b_mod, float* __restrict__ out)
{
    __shared__ float As[64][64];   // [k][b] = h_last slab
    __shared__ float Bs[64][64];   // [k][c']
    const int n0 = blockIdx.x * 64;
    const int tid = threadIdx.x;
    const int tx = tid & 15, ty = tid >> 4;
    const float* zlast = g_xprojT + (long)(NT - 1) * NH * NB;
    float acc[4][4] = {};

    for (int s = 0; s < 16; s++) {
        __syncthreads();
        #pragma unroll
        for (int it = 0; it < 4; it++) {
            int f4 = it * 256 + tid;            // 1024 float4 in slab
            int n = s * 64 + (f4 >> 4);
            float4 z = __ldcg((const float4*)zlast + s * 1024 + f4);
            float bm = __ldg(&b_mod[n]);
            float4 h;
            h.x = modrelu(z.x, bm); h.y = modrelu(z.y, bm);
            h.z = modrelu(z.z, bm); h.w = modrelu(z.w, bm);
            ((float4*)As)[f4] = h;
        }
        #pragma unroll
        for (int it = 0; it < 4; it++) {
            int f4 = it * 256 + tid;
            int np = f4 >> 4, k0 = (f4 & 15) * 4;
            int row = n0 + np; if (row >= NC) row = NC - 1;
            float4 w = *(const float4*)(w_fc + (long)row * NH + s * 64 + k0);
            Bs[k0 + 0][np] = w.x; Bs[k0 + 1][np] = w.y;
            Bs[k0 + 2][np] = w.z; Bs[k0 + 3][np] = w.w;
        }
        __syncthreads();
        #pragma unroll 8
        for (int kk = 0; kk < 64; kk++) {
            float4 av = *(const float4*)(&As[kk][ty * 4]);
            float4 bv = *(const float4*)(&Bs[kk][tx * 4]);
            float a[4] = {av.x, av.y, av.z, av.w};
            float b[4] = {bv.x, bv.y, bv.z, bv.w};
            #pragma unroll
            for (int i = 0; i < 4; i++)
                #pragma unroll
                for (int j = 0; j < 4; j++)
                    acc[i][j] += a[i] * b[j];
        }
    }
    #pragma unroll
    for (int i = 0; i < 4; i++) {
        #pragma unroll
        for (int j = 0; j < 4; j++) {
            int c = n0 + tx * 4 + j;
            if (c < NC) out[(long)(ty * 4 + i) * NC + c] = acc[i][j] + __ldg(&b_fc[c]);
        }
    }
}

// ---------------- launch ----------------
extern "C" void kernel_launch(void* const* d_in, const int* in_sizes, int n_in,
                              void* d_out, int out_size)
{
    const float* x     = (const float*)d_in[0];  // [64,1024,256]
    const float* w_ih  = (const float*)d_in[1];  // [1024,256]
    const float* w_hh  = (const float*)d_in[2];  // [1024,1024]
    const float* b_mod = (const float*)d_in[3];  // [1024]
    const float* w_fc  = (const float*)d_in[4];  // [1000,1024]
    const float* b_fc  = (const float*)d_in[5];  // [1000]
    float* out = (float*)d_out;                  // [64,1000]

    cudaFuncSetAttribute(recur_kernel, cudaFuncAttributeMaxDynamicSharedMemorySize, 98304);

    init_kernel<<<1, 32>>>();
    dim3 gx(NT, NH / 64);
    xproj_kernel<<<gx, 256>>>(x, w_ih);
    recur_kernel<<<RCTAS, 256, 98304>>>(w_hh, b_mod);
    fc_kernel<<<(NC + 63) / 64, 256>>>(w_fc, b_fc, b_mod, out);
}

// round 5
// speedup vs baseline: 2.0633x; 1.3521x over previous
#include <cuda_runtime.h>
#include <math.h>

#define NB 64      // batch
#define NT 1024    // seq len
#define ND 256     // input dim
#define NH 1024    // hidden
#define NC 1000    // classes
#define RCTAS 128  // persistent recurrence CTAs (1 CTA/SM resident)

typedef unsigned long long u64;

// ---------------- scratch (device globals) ----------------
// g_xprojT[t] starts as xproj_t (written by xproj_kernel); the recurrence
// red-accumulates W_hh*h_{t-1} into slice t. h_t = modrelu(z_t) is computed
// on the fly by readers (stage / fc).
__device__ float g_xprojT[NT * NH * NB];   // [t][n][b]  256 MB
__device__ unsigned g_arr[16];             // per n-column-group arrival counters

// ---------------- sync primitives ----------------
__device__ __forceinline__ unsigned ld_acq(const unsigned* p) {
    unsigned v;
    asm volatile("ld.global.acquire.gpu.u32 %0, [%1];" : "=r"(v) : "l"(p));
    return v;
}

// packed f32x2 FMA: d = a*b + d
#define FMA2(d, a, b) asm("fma.rn.f32x2 %0, %1, %2, %0;" : "+l"(d) : "l"(a), "l"(b))
__device__ __forceinline__ float lo32(u64 v) { return __uint_as_float((unsigned)v); }
__device__ __forceinline__ float hi32(u64 v) { return __uint_as_float((unsigned)(v >> 32)); }

// vector atomic add (fire-and-forget), 16B aligned
__device__ __forceinline__ void red_add_v4(float* p, float v0, float v1, float v2, float v3) {
    asm volatile("red.global.add.v4.f32 [%0], {%1, %2, %3, %4};"
                 :: "l"(p), "f"(v0), "f"(v1), "f"(v2), "f"(v3) : "memory");
}

__device__ __forceinline__ float modrelu(float z, float bm) {
    float a = fabsf(z) + bm;
    return (a > 0.0f) ? copysignf(a, z) : 0.0f;
}

// ---------------- init: reset dataflow counters each launch ----------------
__global__ void init_kernel() {
    if (threadIdx.x < 16) g_arr[threadIdx.x] = 0u;
}

// ---------------- classic fp32 tile core (xproj only) ----------------
__device__ __forceinline__ void mm_tile(
    const float* A, int lda,
    const float* B, int ldb, int brows,
    int K, float acc[4][4],
    float (*As)[64], float (*Bs)[64])
{
    const int tid = threadIdx.x;
    const int tx = tid & 15, ty = tid >> 4;
    const int lr = tid >> 2, lc = tid & 3;
    const int br = (lr < brows) ? lr : (brows - 1);
    const float* Arow = A + (long)lr * lda;
    const float* Brow = B + (long)br * ldb;

    for (int k0 = 0; k0 < K; k0 += 32) {
        float4 a0 = __ldcg((const float4*)(Arow + k0 + lc * 4));
        float4 a1 = __ldcg((const float4*)(Arow + k0 + 16 + lc * 4));
        float4 b0 = __ldcg((const float4*)(Brow + k0 + lc * 4));
        float4 b1 = __ldcg((const float4*)(Brow + k0 + 16 + lc * 4));
        __syncthreads();
        As[lc * 4 + 0][lr] = a0.x;  As[lc * 4 + 1][lr] = a0.y;
        As[lc * 4 + 2][lr] = a0.z;  As[lc * 4 + 3][lr] = a0.w;
        As[lc * 4 + 16][lr] = a1.x; As[lc * 4 + 17][lr] = a1.y;
        As[lc * 4 + 18][lr] = a1.z; As[lc * 4 + 19][lr] = a1.w;
        Bs[lc * 4 + 0][lr] = b0.x;  Bs[lc * 4 + 1][lr] = b0.y;
        Bs[lc * 4 + 2][lr] = b0.z;  Bs[lc * 4 + 3][lr] = b0.w;
        Bs[lc * 4 + 16][lr] = b1.x; Bs[lc * 4 + 17][lr] = b1.y;
        Bs[lc * 4 + 18][lr] = b1.z; Bs[lc * 4 + 19][lr] = b1.w;
        __syncthreads();
        #pragma unroll
        for (int kk = 0; kk < 32; kk++) {
            float4 av = *(const float4*)(&As[kk][ty * 4]);
            float4 bv = *(const float4*)(&Bs[kk][tx * 4]);
            float a[4] = {av.x, av.y, av.z, av.w};
            float b[4] = {bv.x, bv.y, bv.z, bv.w};
            #pragma unroll
            for (int i = 0; i < 4; i++)
                #pragma unroll
                for (int j = 0; j < 4; j++)
                    acc[i][j] += a[i] * b[j];
        }
    }
}

// ---------------- kernel 1: xprojT[t][n][b] = x[b][t][:] . w_ih[n][:] ----------------
__global__ __launch_bounds__(256) void xproj_kernel(
    const float* __restrict__ x, const float* __restrict__ w_ih)
{
    __shared__ float As[32][64];
    __shared__ float Bs[32][64];
    const int t0 = blockIdx.x;
    const int n0 = blockIdx.y * 64;
    float acc[4][4] = {};
    mm_tile(x + (long)t0 * ND, NT * ND, w_ih + (long)n0 * ND, ND, 64, ND, acc, As, Bs);

    const int tid = threadIdx.x;
    const int tx = tid & 15, ty = tid >> 4;
    #pragma unroll
    for (int j = 0; j < 4; j++) {
        float4 v = make_float4(acc[0][j], acc[1][j], acc[2][j], acc[3][j]);
        *(float4*)(g_xprojT + ((long)t0 * NH + n0 + tx * 4 + j) * NB + ty * 4) = v;
    }
}

// ---------------- kernel 2: persistent recurrence (dataflow sync, no barrier) ----------------
// CTA (nc = cta&15, kc = cta>>4). Persistent Bs = W_hh[nc*64..+64][kc*128..+128].
// Step t (t=1..NT-1):
//   wait: groups {2kc, 2kc+1} of z_{t-1} complete (arr >= 8*(t-1))
//   stage: h = modrelu(z_{t-1}) chunk kc, duplicated into smem
//   GEMM (FFMA2) -> partial z ; red.add.v4 into g_xprojT[t] ; fence ; arrive arr[nc]
__global__ __launch_bounds__(256) void recur_kernel(
    const float* __restrict__ w_hh, const float* __restrict__ b_mod)
{
    extern __shared__ float sm[];
    float* As_dup = sm;                 // [128][128] floats, (h,h) duplicated pairs, 64 KB
    float* Bs = sm + 128 * 128;         // [128][64] floats (k-major), 32 KB

    const int tid = threadIdx.x;
    const int cta = blockIdx.x;
    const int nc = cta & 15;
    const int kc = cta >> 4;
    const int tx = tid & 15, ty = tid >> 4;

    // ---- one-time: W_hh slice transposed into persistent smem ----
    #pragma unroll
    for (int it = 0; it < 8; it++) {
        int f4 = it * 256 + tid;                 // 2048 float4 = 8192 floats
        int np = f4 >> 5, k0 = (f4 & 31) * 4;
        float4 w = __ldg((const float4*)(w_hh + (long)(nc * 64 + np) * NH + kc * 128 + k0));
        Bs[(k0 + 0) * 64 + np] = w.x;
        Bs[(k0 + 1) * 64 + np] = w.y;
        Bs[(k0 + 2) * 64 + np] = w.z;
        Bs[(k0 + 3) * 64 + np] = w.w;
    }
    __syncthreads();

    for (int t = 1; t < NT; t++) {
        // ---- wait: the two column groups covering chunk kc of z_{t-1} ----
        if (t > 1) {
            unsigned target = (unsigned)(8 * (t - 1));
            if (tid == 0) while (ld_acq(&g_arr[2 * kc]) < target) {}
            if (tid == 1) while (ld_acq(&g_arr[2 * kc + 1]) < target) {}
            __syncthreads();
        }

        // ---- stage: h_{t-1} = modrelu(z_{t-1}) chunk kc, duplicated ----
        {
            const float2* zsrc = (const float2*)(g_xprojT +
                                 ((long)(t - 1) * NH + kc * 128) * NB);
            float4* Ad4 = (float4*)As_dup;
            #pragma unroll
            for (int it = 0; it < 16; it++) {
                int f2 = it * 256 + tid;
                int n = kc * 128 + (f2 >> 5);
                float2 z = __ldcg(&zsrc[f2]);
                float bm = __ldg(&b_mod[n]);
                float hx = modrelu(z.x, bm);
                float hy = modrelu(z.y, bm);
                Ad4[f2] = make_float4(hx, hx, hy, hy);
            }
        }
        __syncthreads();

        // ---- GEMM: 128 kk x (3 LDS.128 + 8 FFMA2) ----
        u64 acc[4][2];
        #pragma unroll
        for (int i = 0; i < 4; i++) { acc[i][0] = 0ull; acc[i][1] = 0ull; }

        #pragma unroll 8
        for (int kk = 0; kk < 128; kk++) {
            const ulonglong2 bp  = *(const ulonglong2*)(Bs + kk * 64 + tx * 4);
            const ulonglong2 a01 = *(const ulonglong2*)(As_dup + kk * 128 + ty * 8);
            const ulonglong2 a23 = *(const ulonglong2*)(As_dup + kk * 128 + ty * 8 + 4);
            FMA2(acc[0][0], a01.x, bp.x); FMA2(acc[0][1], a01.x, bp.y);
            FMA2(acc[1][0], a01.y, bp.x); FMA2(acc[1][1], a01.y, bp.y);
            FMA2(acc[2][0], a23.x, bp.x); FMA2(acc[2][1], a23.x, bp.y);
            FMA2(acc[3][0], a23.y, bp.x); FMA2(acc[3][1], a23.y, bp.y);
        }

        // ---- red-accumulate partials into z_t (vector atomics) ----
        {
            float* zdst = g_xprojT + ((long)t * NH + nc * 64) * NB;
            #pragma unroll
            for (int j = 0; j < 4; j++) {
                int jp = j >> 1;
                float v0, v1, v2, v3;
                if (j & 1) { v0 = hi32(acc[0][jp]); v1 = hi32(acc[1][jp]);
                             v2 = hi32(acc[2][jp]); v3 = hi32(acc[3][jp]); }
                else       { v0 = lo32(acc[0][jp]); v1 = lo32(acc[1][jp]);
                             v2 = lo32(acc[2][jp]); v3 = lo32(acc[3][jp]); }
                red_add_v4(zdst + (long)(tx * 4 + j) * NB + ty * 4, v0, v1, v2, v3);
            }
        }

        // ---- arrive: our reds for step t are visible ----
        __syncthreads();
        if (tid == 0) {
            __threadfence();               // drain reds
            atomicAdd(&g_arr[nc], 1u);
        }
    }
}

// ---------------- kernel 3: fc head out[b][c] = modrelu(z_last)[:,b] . w_fc[c][:] + b_fc[c]
__global__ __launch_bounds__(256) void fc_kernel(
    const float* __restrict__ w_fc, const float* __restrict__ b_fc,
    const float* __restrict__ b_mod, float* __restrict__ out)
{
    __shared__ float As[64][64];   // [k][b] = h_last slab
    __shared__ float Bs[64][64];   // [k][c']
    const int n0 = blockIdx.x * 64;
    const int tid = threadIdx.x;
    const int tx = tid & 15, ty = tid >> 4;
    const float* zlast = g_xprojT + (long)(NT - 1) * NH * NB;
    float acc[4][4] = {};

    for (int s = 0; s < 16; s++) {
        __syncthreads();
        #pragma unroll
        for (int it = 0; it < 4; it++) {
            int f4 = it * 256 + tid;            // 1024 float4 in slab
            int n = s * 64 + (f4 >> 4);
            float4 z = __ldcg((const float4*)zlast + s * 1024 + f4);
            float bm = __ldg(&b_mod[n]);
            float4 h;
            h.x = modrelu(z.x, bm); h.y = modrelu(z.y, bm);
            h.z = modrelu(z.z, bm); h.w = modrelu(z.w, bm);
            ((float4*)As)[f4] = h;
        }
        #pragma unroll
        for (int it = 0; it < 4; it++) {
            int f4 = it * 256 + tid;
            int np = f4 >> 4, k0 = (f4 & 15) * 4;
            int row = n0 + np; if (row >= NC) row = NC - 1;
            float4 w = *(const float4*)(w_fc + (long)row * NH + s * 64 + k0);
            Bs[k0 + 0][np] = w.x; Bs[k0 + 1][np] = w.y;
            Bs[k0 + 2][np] = w.z; Bs[k0 + 3][np] = w.w;
        }
        __syncthreads();
        #pragma unroll 8
        for (int kk = 0; kk < 64; kk++) {
            float4 av = *(const float4*)(&As[kk][ty * 4]);
            float4 bv = *(const float4*)(&Bs[kk][tx * 4]);
            float a[4] = {av.x, av.y, av.z, av.w};
            float b[4] = {bv.x, bv.y, bv.z, bv.w};
            #pragma unroll
            for (int i = 0; i < 4; i++)
                #pragma unroll
                for (int j = 0; j < 4; j++)
                    acc[i][j] += a[i] * b[j];
        }
    }
    #pragma unroll
    for (int i = 0; i < 4; i++) {
        #pragma unroll
        for (int j = 0; j < 4; j++) {
            int c = n0 + tx * 4 + j;
            if (c < NC) out[(long)(ty * 4 + i) * NC + c] = acc[i][j] + __ldg(&b_fc[c]);
        }
    }
}

// ---------------- launch ----------------
extern "C" void kernel_launch(void* const* d_in, const int* in_sizes, int n_in,
                              void* d_out, int out_size)
{
    const float* x     = (const float*)d_in[0];  // [64,1024,256]
    const float* w_ih  = (const float*)d_in[1];  // [1024,256]
    const float* w_hh  = (const float*)d_in[2];  // [1024,1024]
    const float* b_mod = (const float*)d_in[3];  // [1024]
    const float* w_fc  = (const float*)d_in[4];  // [1000,1024]
    const float* b_fc  = (const float*)d_in[5];  // [1000]
    float* out = (float*)d_out;                  // [64,1000]

    cudaFuncSetAttribute(recur_kernel, cudaFuncAttributeMaxDynamicSharedMemorySize, 98304);

    init_kernel<<<1, 32>>>();
    dim3 gx(NT, NH / 64);
    xproj_kernel<<<gx, 256>>>(x, w_ih);
    recur_kernel<<<RCTAS, 256, 98304>>>(w_hh, b_mod);
    fc_kernel<<<(NC + 63) / 64, 256>>>(w_fc, b_fc, b_mod, out);
}